// round 1
// baseline (speedup 1.0000x reference)
#include <cuda_runtime.h>
#include <math.h>
#include <stdint.h>

#define Bv 8
#define Hv 256
#define Pv 1024
#define Kv 32
#define Ev 4
#define BNv 64
#define W1S (2*Hv + Ev)   // 516

// Precomputed current-term (+b1 folded): [b][o][p]
__device__ float g_curterm[Bv * BNv * Pv];

// ---------------------------------------------------------------------------
// Kernel 1: cur_term[b,o,p] = sum_c current[b,c,p] * w1[o,c] + b1[o]
// grid = 128 blocks (b x 16 p-tiles of 64), 256 threads
// ---------------------------------------------------------------------------
__global__ __launch_bounds__(256) void curterm_kernel(
    const float* __restrict__ cur,
    const float* __restrict__ w1,
    const float* __restrict__ b1)
{
    const int blk = blockIdx.x;
    const int b  = blk >> 4;
    const int p0 = (blk & 15) << 6;
    const int t  = threadIdx.x;
    const int po = t & 63;
    const int og = t >> 6;          // 0..3 -> 16 o's each

    __shared__ float s_cur[64 * 64];
    __shared__ float s_w[64 * 68];

    float acc[16];
#pragma unroll
    for (int i = 0; i < 16; ++i) acc[i] = 0.f;

    for (int c0 = 0; c0 < Hv; c0 += 64) {
        __syncthreads();
#pragma unroll
        for (int i = 0; i < 16; ++i) {             // current chunk [c][p]
            int idx = t + i * 256;
            int c = idx >> 6, pp = idx & 63;
            s_cur[c * 64 + pp] = cur[((size_t)(b * Hv + c0 + c)) * Pv + p0 + pp];
        }
#pragma unroll
        for (int i = 0; i < 16; ++i) {             // w1c chunk transposed [c][o]
            int idx = t + i * 256;
            int o = idx >> 6, c = idx & 63;
            s_w[c * 68 + o] = w1[o * W1S + c0 + c];
        }
        __syncthreads();
#pragma unroll 4
        for (int cc = 0; cc < 64; ++cc) {
            float x = s_cur[cc * 64 + po];
            const float4* wr = (const float4*)&s_w[cc * 68 + og * 16];
#pragma unroll
            for (int j = 0; j < 4; ++j) {
                float4 w4 = wr[j];
                acc[j * 4 + 0] += x * w4.x;
                acc[j * 4 + 1] += x * w4.y;
                acc[j * 4 + 2] += x * w4.z;
                acc[j * 4 + 3] += x * w4.w;
            }
        }
    }
#pragma unroll
    for (int i = 0; i < 16; ++i) {
        int o = og * 16 + i;
        g_curterm[((size_t)(b * BNv) + o) * Pv + p0 + po] = acc[i] + b1[o];
    }
}

// ---------------------------------------------------------------------------
// Kernel 2: main fused attention-aggregation. One CTA per (b,p).
// SMEM layout (floats):
//   sw1nT [256][65]  w1n transposed
//   snbr  [256][36]  neighbor tile (rows padded)
//   sedge [4][32]
//   sw1e  [64][4]
//   spart [8][32]    per-warp logit partials
//   swgt  [32]       softmax weights
// ---------------------------------------------------------------------------
#define SW1NT_OFF 0
#define SNBR_OFF  (256 * 65)
#define SEDGE_OFF (SNBR_OFF + 256 * 36)
#define SW1E_OFF  (SEDGE_OFF + 128)
#define SPART_OFF (SW1E_OFF + 256)
#define SWGT_OFF  (SPART_OFF + 256)
#define SMEM_FLOATS (SWGT_OFF + 32)
#define SMEM_BYTES  (SMEM_FLOATS * 4)

__global__ __launch_bounds__(256, 2) void attn_kernel(
    const float* __restrict__ nbr,
    const float* __restrict__ vld,
    const float* __restrict__ edg,
    const float* __restrict__ w1,
    const float* __restrict__ w2,
    const float* __restrict__ b2,
    float* __restrict__ out)
{
    extern __shared__ float sm[];
    float* sw1nT = sm + SW1NT_OFF;
    float* snbr  = sm + SNBR_OFF;
    float* sedge = sm + SEDGE_OFF;
    float* sw1e  = sm + SW1E_OFF;
    float* spart = sm + SPART_OFF;
    float* swgt  = sm + SWGT_OFF;

    const int t = threadIdx.x;
    const int b = blockIdx.x >> 10;
    const int p = blockIdx.x & 1023;

    // ---- stage w1n transposed: sw1nT[c*65 + o] ----
#pragma unroll
    for (int i = 0; i < 16; ++i) {
        int idx = t + i * 256;                 // 4096 float4s
        int o  = idx >> 6;
        int c4 = (idx & 63) << 2;
        float4 v = *(const float4*)&w1[o * W1S + Hv + c4];
        sw1nT[(c4 + 0) * 65 + o] = v.x;
        sw1nT[(c4 + 1) * 65 + o] = v.y;
        sw1nT[(c4 + 2) * 65 + o] = v.z;
        sw1nT[(c4 + 3) * 65 + o] = v.w;
    }
    // ---- stage neighbor tile: snbr[c*36 + k] ----
    {
        const float* base = nbr + ((size_t)(b * Hv)) * Pv * Kv + (size_t)p * Kv;
#pragma unroll
        for (int i = 0; i < 8; ++i) {
            int idx = t + i * 256;             // 2048 float4s
            int c  = idx >> 3;
            int k4 = (idx & 7) << 2;
            float4 v = *(const float4*)&base[(size_t)c * (Pv * Kv) + k4];
            *(float4*)&snbr[c * 36 + k4] = v;
        }
    }
    // ---- edge tile + w1e ----
    if (t < 128) {
        int e = t >> 5, k = t & 31;
        sedge[t] = edg[(((size_t)(b * Ev + e)) * Pv + p) * Kv + k];
    }
    {
        int o = t >> 2, e = t & 3;
        sw1e[t] = w1[o * W1S + 2 * Hv + e];
    }
    __syncthreads();

    // ---- main GEMM: hid[o][k] for o = t>>2, k in [k0, k0+8) ----
    const int o  = t >> 2;
    const int kg = t & 3;
    const int k0 = kg << 3;

    unsigned long long acc0 = 0ull, acc1 = 0ull, acc2 = 0ull, acc3 = 0ull;

#pragma unroll 4
    for (int c = 0; c < Hv; ++c) {
        float a = sw1nT[c * 65 + o];
        unsigned long long a2;
        asm("mov.b64 %0, {%1, %1};" : "=l"(a2) : "f"(a));
        const ulonglong2 v01 = *(const ulonglong2*)&snbr[c * 36 + k0];
        const ulonglong2 v23 = *(const ulonglong2*)&snbr[c * 36 + k0 + 4];
        asm("fma.rn.f32x2 %0, %1, %2, %0;" : "+l"(acc0) : "l"(v01.x), "l"(a2));
        asm("fma.rn.f32x2 %0, %1, %2, %0;" : "+l"(acc1) : "l"(v01.y), "l"(a2));
        asm("fma.rn.f32x2 %0, %1, %2, %0;" : "+l"(acc2) : "l"(v23.x), "l"(a2));
        asm("fma.rn.f32x2 %0, %1, %2, %0;" : "+l"(acc3) : "l"(v23.y), "l"(a2));
    }

    float hv[8];
    asm("mov.b64 {%0, %1}, %2;" : "=f"(hv[0]), "=f"(hv[1]) : "l"(acc0));
    asm("mov.b64 {%0, %1}, %2;" : "=f"(hv[2]), "=f"(hv[3]) : "l"(acc1));
    asm("mov.b64 {%0, %1}, %2;" : "=f"(hv[4]), "=f"(hv[5]) : "l"(acc2));
    asm("mov.b64 {%0, %1}, %2;" : "=f"(hv[6]), "=f"(hv[7]) : "l"(acc3));

    // ---- epilogue: + cur_term + edge_term, relu, * w2[o] ----
    {
        float basev = g_curterm[((size_t)(b * BNv) + o) * Pv + p];
        float w2o = __ldg(&w2[o]);
        float4 we = *(const float4*)&sw1e[o * 4];
#pragma unroll
        for (int kk = 0; kk < 8; ++kk) {
            int k = k0 + kk;
            float h = hv[kk] + basev
                    + we.x * sedge[k]       + we.y * sedge[32 + k]
                    + we.z * sedge[64 + k]  + we.w * sedge[96 + k];
            hv[kk] = fmaxf(h, 0.f) * w2o;
        }
    }
    // ---- reduce over the 8 o's within each warp (lane bits 2..4) ----
#pragma unroll
    for (int kk = 0; kk < 8; ++kk) {
        float r = hv[kk];
        r += __shfl_xor_sync(0xffffffffu, r, 4);
        r += __shfl_xor_sync(0xffffffffu, r, 8);
        r += __shfl_xor_sync(0xffffffffu, r, 16);
        hv[kk] = r;
    }
    if ((t & 31) < 4) {
        int w = t >> 5;
#pragma unroll
        for (int kk = 0; kk < 8; ++kk)
            spart[w * 32 + (t & 3) * 8 + kk] = hv[kk];
    }
    __syncthreads();

    // ---- masked softmax over K (warp 0 only) ----
    if (t < 32) {
        float lg = __ldg(b2);
#pragma unroll
        for (int w = 0; w < 8; ++w) lg += spart[w * 32 + t];
        bool valid = vld[(((size_t)(b * Pv)) + p) * Kv + t] > 0.5f;
        unsigned msk = __ballot_sync(0xffffffffu, valid);
        const float NEG_INF = __int_as_float(0xff800000);
        float l = valid ? lg : NEG_INF;
        float m = l;
#pragma unroll
        for (int d = 16; d; d >>= 1) m = fmaxf(m, __shfl_xor_sync(0xffffffffu, m, d));
        float e = (msk != 0u) ? expf(l - m) : 0.f;   // invalid lanes: exp(-inf)=0
        float s = e;
#pragma unroll
        for (int d = 16; d; d >>= 1) s += __shfl_xor_sync(0xffffffffu, s, d);
        swgt[t] = (msk != 0u) ? (e / s) : 0.f;
    }
    __syncthreads();

    // ---- pooled[c] = sum_k nbr[c][k] * w[k]; thread = c ----
    {
        float sum = 0.f;
        const float4* row = (const float4*)&snbr[t * 36];
#pragma unroll
        for (int q = 0; q < 8; ++q) {
            float4 v  = row[q];
            float4 wv = *(const float4*)&swgt[q * 4];
            sum += v.x * wv.x + v.y * wv.y + v.z * wv.z + v.w * wv.w;
        }
        out[((size_t)(b * Hv) + t) * Pv + p] = sum;
    }
}

// ---------------------------------------------------------------------------
extern "C" void kernel_launch(void* const* d_in, const int* in_sizes, int n_in,
                              void* d_out, int out_size)
{
    const float* cur = (const float*)d_in[0];
    const float* nbr = (const float*)d_in[1];
    const float* vld = (const float*)d_in[2];
    const float* edg = (const float*)d_in[3];
    const float* w1  = (const float*)d_in[4];
    const float* b1  = (const float*)d_in[5];
    const float* w2  = (const float*)d_in[6];
    const float* b2  = (const float*)d_in[7];
    float* out = (float*)d_out;

    curterm_kernel<<<128, 256>>>(cur, w1, b1);

    cudaFuncSetAttribute(attn_kernel,
                         cudaFuncAttributeMaxDynamicSharedMemorySize, SMEM_BYTES);
    attn_kernel<<<Bv * Pv, 256, SMEM_BYTES>>>(nbr, vld, edg, w1, w2, b2, out);
}

// round 2
// speedup vs baseline: 2.0103x; 2.0103x over previous
#include <cuda_runtime.h>
#include <math.h>
#include <stdint.h>

#define Bv 8
#define Hv 256
#define Pv 1024
#define Kv 32
#define Ev 4
#define BNv 64
#define W1S (2*Hv + Ev)   // 516

typedef unsigned long long ull;

// Precomputed current-term (+b1 folded): [b][p][o]
__device__ float g_curterm[Bv * Pv * BNv];
// Pre-transposed w1n: [c][o]
__device__ float g_w1nT[Hv * BNv];

// ---------------------------------------------------------------------------
// Kernel 0: transpose w1n -> g_w1nT[c*64 + o]
// ---------------------------------------------------------------------------
__global__ __launch_bounds__(256) void w1nT_kernel(const float* __restrict__ w1)
{
    int idx = blockIdx.x * 256 + threadIdx.x;   // grid 64 -> 16384
    int o = idx & 63;
    int c = idx >> 6;
    g_w1nT[c * 64 + o] = w1[o * W1S + Hv + c];
}

// ---------------------------------------------------------------------------
// Kernel 1: cur_term[b,p,o] = sum_c current[b,c,p] * w1[o,c] + b1[o]
// grid = 128 blocks (b x 16 p-tiles of 64), 256 threads
// ---------------------------------------------------------------------------
__global__ __launch_bounds__(256) void curterm_kernel(
    const float* __restrict__ cur,
    const float* __restrict__ w1,
    const float* __restrict__ b1)
{
    const int blk = blockIdx.x;
    const int b  = blk >> 4;
    const int p0 = (blk & 15) << 6;
    const int t  = threadIdx.x;
    const int po = t & 63;
    const int og = t >> 6;          // 0..3 -> 16 o's each

    __shared__ float s_cur[64 * 64];
    __shared__ float s_w[64 * 68];

    float acc[16];
#pragma unroll
    for (int i = 0; i < 16; ++i) acc[i] = 0.f;

    for (int c0 = 0; c0 < Hv; c0 += 64) {
        __syncthreads();
#pragma unroll
        for (int i = 0; i < 16; ++i) {             // current chunk [c][p]
            int idx = t + i * 256;
            int c = idx >> 6, pp = idx & 63;
            s_cur[c * 64 + pp] = cur[((size_t)(b * Hv + c0 + c)) * Pv + p0 + pp];
        }
#pragma unroll
        for (int i = 0; i < 16; ++i) {             // w1c chunk transposed [c][o]
            int idx = t + i * 256;
            int o = idx >> 6, c = idx & 63;
            s_w[c * 68 + o] = w1[o * W1S + c0 + c];
        }
        __syncthreads();
#pragma unroll 4
        for (int cc = 0; cc < 64; ++cc) {
            float x = s_cur[cc * 64 + po];
            const float4* wr = (const float4*)&s_w[cc * 68 + og * 16];
#pragma unroll
            for (int j = 0; j < 4; ++j) {
                float4 w4 = wr[j];
                acc[j * 4 + 0] += x * w4.x;
                acc[j * 4 + 1] += x * w4.y;
                acc[j * 4 + 2] += x * w4.z;
                acc[j * 4 + 3] += x * w4.w;
            }
        }
    }
    // write [b][p][o]
    float* dst = &g_curterm[((size_t)b * Pv + p0 + po) * BNv + og * 16];
#pragma unroll
    for (int j = 0; j < 4; ++j) {
        float4 v;
        v.x = acc[j*4+0] + b1[og*16 + j*4 + 0];
        v.y = acc[j*4+1] + b1[og*16 + j*4 + 1];
        v.z = acc[j*4+2] + b1[og*16 + j*4 + 2];
        v.w = acc[j*4+3] + b1[og*16 + j*4 + 3];
        *(float4*)&dst[j*4] = v;
    }
}

// ---------------------------------------------------------------------------
// Kernel 2: fused attention-aggregation. One CTA (128 thr) per (b,p).
// Thread tile: 4o x 4k. f32x2 FMAs, acc pairs packed over o.
// SMEM (floats):
//   sw1nT [256][64]   w1n transposed (no pad needed; uniform row per warp)
//   snbr  [256][36]   neighbor tile
//   sedgeT[32][4]     edge transposed
//   sw1e  [64][4]
//   spart [4][32]
//   swgt  [32]
// ---------------------------------------------------------------------------
#define SW1NT_OFF 0
#define SNBR_OFF  (256 * 64)
#define SEDGET_OFF (SNBR_OFF + 256 * 36)
#define SW1E_OFF  (SEDGET_OFF + 128)
#define SPART_OFF (SW1E_OFF + 256)
#define SWGT_OFF  (SPART_OFF + 128)
#define SMEM_FLOATS (SWGT_OFF + 32)
#define SMEM_BYTES  (SMEM_FLOATS * 4)

__global__ __launch_bounds__(128, 2) void attn_kernel(
    const float* __restrict__ nbr,
    const float* __restrict__ vld,
    const float* __restrict__ edg,
    const float* __restrict__ w1,
    const float* __restrict__ w2,
    const float* __restrict__ b2,
    float* __restrict__ out)
{
    extern __shared__ float sm[];
    float* sw1nT  = sm + SW1NT_OFF;
    float* snbr   = sm + SNBR_OFF;
    float* sedgeT = sm + SEDGET_OFF;
    float* sw1e   = sm + SW1E_OFF;
    float* spart  = sm + SPART_OFF;
    float* swgt   = sm + SWGT_OFF;

    const int t = threadIdx.x;
    const int b = blockIdx.x >> 10;
    const int p = blockIdx.x & 1023;

    // ---- stage w1nT: straight vectorized copy (4096 float4) ----
    {
        const float4* g4 = (const float4*)g_w1nT;
        float4* s4 = (float4*)sw1nT;
#pragma unroll
        for (int i = 0; i < 32; ++i)
            s4[t + i * 128] = g4[t + i * 128];
    }
    // ---- stage neighbor tile: snbr[c*36 + k] (2048 float4) ----
    {
        const float* base = nbr + ((size_t)(b * Hv)) * Pv * Kv + (size_t)p * Kv;
#pragma unroll
        for (int i = 0; i < 16; ++i) {
            int idx = t + i * 128;
            int c  = idx >> 3;
            int k4 = (idx & 7) << 2;
            float4 v = *(const float4*)&base[(size_t)c * (Pv * Kv) + k4];
            *(float4*)&snbr[c * 36 + k4] = v;
        }
    }
    // ---- edge tile (transposed [k][e]) + w1e ----
    {
        int e = t >> 5, k = t & 31;                 // t<128 covers all
        sedgeT[k * 4 + e] = edg[(((size_t)(b * Ev + e)) * Pv + p) * Kv + k];
    }
#pragma unroll
    for (int i = 0; i < 2; ++i) {
        int idx = t + i * 128;
        int o = idx >> 2, e = idx & 3;
        sw1e[idx] = w1[o * W1S + 2 * Hv + e];
    }
    __syncthreads();

    // ---- main GEMM: thread computes hid[o0..o0+3][k0..k0+3] ----
    const int o0 = (t >> 3) << 2;   // 16 o-tiles
    const int k0 = (t & 7) << 2;    // 8 k-tiles

    // acc[k*2 + j]: packed pair over (o0+2j, o0+2j+1) for column k0+k
    ull acc[8];
#pragma unroll
    for (int i = 0; i < 8; ++i) acc[i] = 0ull;

#pragma unroll 8
    for (int c = 0; c < Hv; ++c) {
        ulonglong2 a2 = *(const ulonglong2*)&sw1nT[c * 64 + o0]; // (a0,a1),(a2,a3)
        float4 bf = *(const float4*)&snbr[c * 36 + k0];
        ull bd0, bd1, bd2, bd3;
        asm("mov.b64 %0, {%1, %1};" : "=l"(bd0) : "f"(bf.x));
        asm("mov.b64 %0, {%1, %1};" : "=l"(bd1) : "f"(bf.y));
        asm("mov.b64 %0, {%1, %1};" : "=l"(bd2) : "f"(bf.z));
        asm("mov.b64 %0, {%1, %1};" : "=l"(bd3) : "f"(bf.w));
        asm("fma.rn.f32x2 %0, %1, %2, %0;" : "+l"(acc[0]) : "l"(a2.x), "l"(bd0));
        asm("fma.rn.f32x2 %0, %1, %2, %0;" : "+l"(acc[1]) : "l"(a2.y), "l"(bd0));
        asm("fma.rn.f32x2 %0, %1, %2, %0;" : "+l"(acc[2]) : "l"(a2.x), "l"(bd1));
        asm("fma.rn.f32x2 %0, %1, %2, %0;" : "+l"(acc[3]) : "l"(a2.y), "l"(bd1));
        asm("fma.rn.f32x2 %0, %1, %2, %0;" : "+l"(acc[4]) : "l"(a2.x), "l"(bd2));
        asm("fma.rn.f32x2 %0, %1, %2, %0;" : "+l"(acc[5]) : "l"(a2.y), "l"(bd2));
        asm("fma.rn.f32x2 %0, %1, %2, %0;" : "+l"(acc[6]) : "l"(a2.x), "l"(bd3));
        asm("fma.rn.f32x2 %0, %1, %2, %0;" : "+l"(acc[7]) : "l"(a2.y), "l"(bd3));
    }

    // unpack: h[oo][kk]
    float h[4][4];
#pragma unroll
    for (int kk = 0; kk < 4; ++kk) {
        asm("mov.b64 {%0, %1}, %2;" : "=f"(h[0][kk]), "=f"(h[1][kk]) : "l"(acc[kk*2]));
        asm("mov.b64 {%0, %1}, %2;" : "=f"(h[2][kk]), "=f"(h[3][kk]) : "l"(acc[kk*2+1]));
    }

    // ---- epilogue: + cur_term + edge_term, relu, * w2[o], partial logits ----
    float lg[4];
    {
        float4 ct  = *(const float4*)&g_curterm[((size_t)b * Pv + p) * BNv + o0];
        float4 w2v = *(const float4*)&w2[o0];
        float4 we0 = *(const float4*)&sw1e[(o0 + 0) * 4];
        float4 we1 = *(const float4*)&sw1e[(o0 + 1) * 4];
        float4 we2 = *(const float4*)&sw1e[(o0 + 2) * 4];
        float4 we3 = *(const float4*)&sw1e[(o0 + 3) * 4];
        const float ctv[4] = {ct.x, ct.y, ct.z, ct.w};
        const float w2a[4] = {w2v.x, w2v.y, w2v.z, w2v.w};
#pragma unroll
        for (int kk = 0; kk < 4; ++kk) {
            float4 ev = *(const float4*)&sedgeT[(k0 + kk) * 4];
            float s = 0.f;
            float e0 = we0.x*ev.x + we0.y*ev.y + we0.z*ev.z + we0.w*ev.w;
            float e1 = we1.x*ev.x + we1.y*ev.y + we1.z*ev.z + we1.w*ev.w;
            float e2 = we2.x*ev.x + we2.y*ev.y + we2.z*ev.z + we2.w*ev.w;
            float e3 = we3.x*ev.x + we3.y*ev.y + we3.z*ev.z + we3.w*ev.w;
            s += fmaxf(h[0][kk] + ctv[0] + e0, 0.f) * w2a[0];
            s += fmaxf(h[1][kk] + ctv[1] + e1, 0.f) * w2a[1];
            s += fmaxf(h[2][kk] + ctv[2] + e2, 0.f) * w2a[2];
            s += fmaxf(h[3][kk] + ctv[3] + e3, 0.f) * w2a[3];
            lg[kk] = s;
        }
    }
    // reduce over the 4 ty-groups within each warp (lane bits 3,4)
#pragma unroll
    for (int kk = 0; kk < 4; ++kk) {
        float r = lg[kk];
        r += __shfl_xor_sync(0xffffffffu, r, 8);
        r += __shfl_xor_sync(0xffffffffu, r, 16);
        lg[kk] = r;
    }
    if ((t & 31) < 8) {
        int w = t >> 5;
        float4 v = {lg[0], lg[1], lg[2], lg[3]};
        *(float4*)&spart[w * 32 + k0] = v;
    }
    __syncthreads();

    // ---- masked softmax over K (warp 0 only) ----
    if (t < 32) {
        float lgk = spart[t] + spart[32 + t] + spart[64 + t] + spart[96 + t]
                  + __ldg(b2);
        bool valid = vld[(((size_t)(b * Pv)) + p) * Kv + t] > 0.5f;
        unsigned msk = __ballot_sync(0xffffffffu, valid);
        const float NEG_INF = __int_as_float(0xff800000);
        float l = valid ? lgk : NEG_INF;
        float m = l;
#pragma unroll
        for (int d = 16; d; d >>= 1) m = fmaxf(m, __shfl_xor_sync(0xffffffffu, m, d));
        float e = (msk != 0u) ? expf(l - m) : 0.f;
        float s = e;
#pragma unroll
        for (int d = 16; d; d >>= 1) s += __shfl_xor_sync(0xffffffffu, s, d);
        swgt[t] = (msk != 0u) ? (e / s) : 0.f;
    }
    __syncthreads();

    // ---- pooled[c] = sum_k nbr[c][k] * w[k]; 2 rows per thread ----
    {
        const int rot = (t >> 3) & 7;   // break bank conflicts of stride-36 columns
#pragma unroll
        for (int r = 0; r < 2; ++r) {
            int c = t + r * 128;
            const float* row = &snbr[c * 36];
            float sum = 0.f;
#pragma unroll
            for (int q = 0; q < 8; ++q) {
                int qq = (q + rot) & 7;
                float4 v  = *(const float4*)&row[qq * 4];
                float4 wv = *(const float4*)&swgt[qq * 4];
                sum += v.x * wv.x + v.y * wv.y + v.z * wv.z + v.w * wv.w;
            }
            out[((size_t)(b * Hv) + c) * Pv + p] = sum;
        }
    }
}

// ---------------------------------------------------------------------------
extern "C" void kernel_launch(void* const* d_in, const int* in_sizes, int n_in,
                              void* d_out, int out_size)
{
    const float* cur = (const float*)d_in[0];
    const float* nbr = (const float*)d_in[1];
    const float* vld = (const float*)d_in[2];
    const float* edg = (const float*)d_in[3];
    const float* w1  = (const float*)d_in[4];
    const float* b1  = (const float*)d_in[5];
    const float* w2  = (const float*)d_in[6];
    const float* b2  = (const float*)d_in[7];
    float* out = (float*)d_out;

    w1nT_kernel<<<64, 256>>>(w1);
    curterm_kernel<<<128, 256>>>(cur, w1, b1);

    cudaFuncSetAttribute(attn_kernel,
                         cudaFuncAttributeMaxDynamicSharedMemorySize, SMEM_BYTES);
    attn_kernel<<<Bv * Pv, 128, SMEM_BYTES>>>(nbr, vld, edg, w1, w2, b2, out);
}

// round 3
// speedup vs baseline: 2.1718x; 1.0803x over previous
#include <cuda_runtime.h>
#include <math.h>
#include <stdint.h>

#define Bv 8
#define Hv 256
#define Pv 1024
#define Kv 32
#define Ev 4
#define BNv 64
#define W1S (2*Hv + Ev)   // 516

typedef unsigned long long ull;

// Precomputed current-term (+b1 folded): [b][p][o]
__device__ float g_curterm[Bv * Pv * BNv];
// Pre-transposed w1n: [c][o]  (64 KB — stays L1-resident in attn_kernel)
__device__ float g_w1nT[Hv * BNv];

// ---------------------------------------------------------------------------
// Kernel 1: cur_term[b,p,o] = sum_c current[b,c,p] * w1[o,c] + b1[o]
// Also blocks 0..63 write the w1n transpose (fused to save a launch).
// grid = 128 blocks (b x 16 p-tiles of 64), 256 threads
// ---------------------------------------------------------------------------
__global__ __launch_bounds__(256) void curterm_kernel(
    const float* __restrict__ cur,
    const float* __restrict__ w1,
    const float* __restrict__ b1)
{
    const int blk = blockIdx.x;
    const int t  = threadIdx.x;

    // fused w1n transpose: 16384 elements over blocks 0..63
    if (blk < 64) {
        int idx = blk * 256 + t;
        int o = idx & 63;
        int c = idx >> 6;
        g_w1nT[c * 64 + o] = w1[o * W1S + Hv + c];
    }

    const int b  = blk >> 4;
    const int p0 = (blk & 15) << 6;
    const int po = t & 63;
    const int og = t >> 6;          // 0..3 -> 16 o's each

    __shared__ float s_cur[64 * 64];
    __shared__ float s_w[64 * 68];

    float acc[16];
#pragma unroll
    for (int i = 0; i < 16; ++i) acc[i] = 0.f;

    for (int c0 = 0; c0 < Hv; c0 += 64) {
        __syncthreads();
#pragma unroll
        for (int i = 0; i < 16; ++i) {             // current chunk [c][p]
            int idx = t + i * 256;
            int c = idx >> 6, pp = idx & 63;
            s_cur[c * 64 + pp] = cur[((size_t)(b * Hv + c0 + c)) * Pv + p0 + pp];
        }
#pragma unroll
        for (int i = 0; i < 16; ++i) {             // w1c chunk transposed [c][o]
            int idx = t + i * 256;
            int o = idx >> 6, c = idx & 63;
            s_w[c * 68 + o] = w1[o * W1S + c0 + c];
        }
        __syncthreads();
#pragma unroll 4
        for (int cc = 0; cc < 64; ++cc) {
            float x = s_cur[cc * 64 + po];
            const float4* wr = (const float4*)&s_w[cc * 68 + og * 16];
#pragma unroll
            for (int j = 0; j < 4; ++j) {
                float4 w4 = wr[j];
                acc[j * 4 + 0] += x * w4.x;
                acc[j * 4 + 1] += x * w4.y;
                acc[j * 4 + 2] += x * w4.z;
                acc[j * 4 + 3] += x * w4.w;
            }
        }
    }
    // write [b][p][o]
    float* dst = &g_curterm[((size_t)b * Pv + p0 + po) * BNv + og * 16];
#pragma unroll
    for (int j = 0; j < 4; ++j) {
        float4 v;
        v.x = acc[j*4+0] + b1[og*16 + j*4 + 0];
        v.y = acc[j*4+1] + b1[og*16 + j*4 + 1];
        v.z = acc[j*4+2] + b1[og*16 + j*4 + 2];
        v.w = acc[j*4+3] + b1[og*16 + j*4 + 3];
        *(float4*)&dst[j*4] = v;
    }
}

// ---------------------------------------------------------------------------
// Kernel 2: fused attention-aggregation. One CTA (128 thr) per (b,p).
// Thread tile: 4o x 4k. a-operand LDG'd from L1-resident g_w1nT.
// SMEM (floats):  snbr[256][36], sedgeT[32][4], sw1e[64][4], spart[4][32], swgt[32]
// 4 CTAs/SM (smem ~39KB) -> 16 warps/SM; L1D keeps the 64KB w1nT hot.
// ---------------------------------------------------------------------------
#define SNBR_OFF   0
#define SEDGET_OFF (256 * 36)
#define SW1E_OFF   (SEDGET_OFF + 128)
#define SPART_OFF  (SW1E_OFF + 256)
#define SWGT_OFF   (SPART_OFF + 128)
#define SMEM_FLOATS (SWGT_OFF + 32)
#define SMEM_BYTES  (SMEM_FLOATS * 4)

__global__ __launch_bounds__(128, 4) void attn_kernel(
    const float* __restrict__ nbr,
    const float* __restrict__ vld,
    const float* __restrict__ edg,
    const float* __restrict__ w1,
    const float* __restrict__ w2,
    const float* __restrict__ b2,
    float* __restrict__ out)
{
    extern __shared__ float sm[];
    float* snbr   = sm + SNBR_OFF;
    float* sedgeT = sm + SEDGET_OFF;
    float* sw1e   = sm + SW1E_OFF;
    float* spart  = sm + SPART_OFF;
    float* swgt   = sm + SWGT_OFF;

    const int t = threadIdx.x;
    const int b = blockIdx.x >> 10;
    const int p = blockIdx.x & 1023;

    // ---- stage neighbor tile: snbr[c*36 + k] (2048 float4) ----
    {
        const float* base = nbr + ((size_t)(b * Hv)) * Pv * Kv + (size_t)p * Kv;
#pragma unroll
        for (int i = 0; i < 16; ++i) {
            int idx = t + i * 128;
            int c  = idx >> 3;
            int k4 = (idx & 7) << 2;
            float4 v = *(const float4*)&base[(size_t)c * (Pv * Kv) + k4];
            *(float4*)&snbr[c * 36 + k4] = v;
        }
    }
    // ---- edge tile (transposed [k][e]) + w1e ----
    {
        int e = t >> 5, k = t & 31;                 // t<128 covers all
        sedgeT[k * 4 + e] = edg[(((size_t)(b * Ev + e)) * Pv + p) * Kv + k];
    }
#pragma unroll
    for (int i = 0; i < 2; ++i) {
        int idx = t + i * 128;
        int o = idx >> 2, e = idx & 3;
        sw1e[idx] = w1[o * W1S + 2 * Hv + e];
    }
    __syncthreads();

    // ---- main GEMM: thread computes hid[o0..o0+3][k0..k0+3] ----
    const int o0 = (t >> 3) << 2;   // 16 o-tiles (warp: 4 contiguous -> 64B LDG)
    const int k0 = (t & 7) << 2;    // 8 k-tiles

    // acc[k*2 + j]: packed pair over (o0+2j, o0+2j+1) for column k0+k
    ull acc[8];
#pragma unroll
    for (int i = 0; i < 8; ++i) acc[i] = 0ull;

    const float* __restrict__ wa = &g_w1nT[o0];

#pragma unroll 8
    for (int c = 0; c < Hv; ++c) {
        ulonglong2 a2 = *(const ulonglong2*)&wa[c * 64];   // LDG.128, L1-hot
        float4 bf = *(const float4*)&snbr[c * 36 + k0];    // LDS.128
        ull bd0, bd1, bd2, bd3;
        asm("mov.b64 %0, {%1, %1};" : "=l"(bd0) : "f"(bf.x));
        asm("mov.b64 %0, {%1, %1};" : "=l"(bd1) : "f"(bf.y));
        asm("mov.b64 %0, {%1, %1};" : "=l"(bd2) : "f"(bf.z));
        asm("mov.b64 %0, {%1, %1};" : "=l"(bd3) : "f"(bf.w));
        asm("fma.rn.f32x2 %0, %1, %2, %0;" : "+l"(acc[0]) : "l"(a2.x), "l"(bd0));
        asm("fma.rn.f32x2 %0, %1, %2, %0;" : "+l"(acc[1]) : "l"(a2.y), "l"(bd0));
        asm("fma.rn.f32x2 %0, %1, %2, %0;" : "+l"(acc[2]) : "l"(a2.x), "l"(bd1));
        asm("fma.rn.f32x2 %0, %1, %2, %0;" : "+l"(acc[3]) : "l"(a2.y), "l"(bd1));
        asm("fma.rn.f32x2 %0, %1, %2, %0;" : "+l"(acc[4]) : "l"(a2.x), "l"(bd2));
        asm("fma.rn.f32x2 %0, %1, %2, %0;" : "+l"(acc[5]) : "l"(a2.y), "l"(bd2));
        asm("fma.rn.f32x2 %0, %1, %2, %0;" : "+l"(acc[6]) : "l"(a2.x), "l"(bd3));
        asm("fma.rn.f32x2 %0, %1, %2, %0;" : "+l"(acc[7]) : "l"(a2.y), "l"(bd3));
    }

    // unpack: h[oo][kk]
    float h[4][4];
#pragma unroll
    for (int kk = 0; kk < 4; ++kk) {
        asm("mov.b64 {%0, %1}, %2;" : "=f"(h[0][kk]), "=f"(h[1][kk]) : "l"(acc[kk*2]));
        asm("mov.b64 {%0, %1}, %2;" : "=f"(h[2][kk]), "=f"(h[3][kk]) : "l"(acc[kk*2+1]));
    }

    // ---- epilogue: + cur_term + edge_term, relu, * w2[o], partial logits ----
    float lg[4];
    {
        float4 ct  = *(const float4*)&g_curterm[((size_t)b * Pv + p) * BNv + o0];
        float4 w2v = *(const float4*)&w2[o0];
        float4 we0 = *(const float4*)&sw1e[(o0 + 0) * 4];
        float4 we1 = *(const float4*)&sw1e[(o0 + 1) * 4];
        float4 we2 = *(const float4*)&sw1e[(o0 + 2) * 4];
        float4 we3 = *(const float4*)&sw1e[(o0 + 3) * 4];
        const float ctv[4] = {ct.x, ct.y, ct.z, ct.w};
        const float w2a[4] = {w2v.x, w2v.y, w2v.z, w2v.w};
#pragma unroll
        for (int kk = 0; kk < 4; ++kk) {
            float4 ev = *(const float4*)&sedgeT[(k0 + kk) * 4];
            float s = 0.f;
            float e0 = we0.x*ev.x + we0.y*ev.y + we0.z*ev.z + we0.w*ev.w;
            float e1 = we1.x*ev.x + we1.y*ev.y + we1.z*ev.z + we1.w*ev.w;
            float e2 = we2.x*ev.x + we2.y*ev.y + we2.z*ev.z + we2.w*ev.w;
            float e3 = we3.x*ev.x + we3.y*ev.y + we3.z*ev.z + we3.w*ev.w;
            s += fmaxf(h[0][kk] + ctv[0] + e0, 0.f) * w2a[0];
            s += fmaxf(h[1][kk] + ctv[1] + e1, 0.f) * w2a[1];
            s += fmaxf(h[2][kk] + ctv[2] + e2, 0.f) * w2a[2];
            s += fmaxf(h[3][kk] + ctv[3] + e3, 0.f) * w2a[3];
            lg[kk] = s;
        }
    }
    // reduce over the 4 o-groups within each warp (lane bits 3,4)
#pragma unroll
    for (int kk = 0; kk < 4; ++kk) {
        float r = lg[kk];
        r += __shfl_xor_sync(0xffffffffu, r, 8);
        r += __shfl_xor_sync(0xffffffffu, r, 16);
        lg[kk] = r;
    }
    if ((t & 31) < 8) {
        int w = t >> 5;
        float4 v = {lg[0], lg[1], lg[2], lg[3]};
        *(float4*)&spart[w * 32 + k0] = v;
    }
    __syncthreads();

    // ---- masked softmax over K (warp 0 only) ----
    if (t < 32) {
        float lgk = spart[t] + spart[32 + t] + spart[64 + t] + spart[96 + t]
                  + __ldg(b2);
        bool valid = vld[(((size_t)(b * Pv)) + p) * Kv + t] > 0.5f;
        unsigned msk = __ballot_sync(0xffffffffu, valid);
        const float NEG_INF = __int_as_float(0xff800000);
        float l = valid ? lgk : NEG_INF;
        float m = l;
#pragma unroll
        for (int d = 16; d; d >>= 1) m = fmaxf(m, __shfl_xor_sync(0xffffffffu, m, d));
        float e = (msk != 0u) ? expf(l - m) : 0.f;
        float s = e;
#pragma unroll
        for (int d = 16; d; d >>= 1) s += __shfl_xor_sync(0xffffffffu, s, d);
        swgt[t] = (msk != 0u) ? (e / s) : 0.f;
    }
    __syncthreads();

    // ---- pooled[c] = sum_k nbr[c][k] * w[k]; 2 rows per thread ----
    {
        const int rot = (t >> 3) & 7;   // break bank conflicts of stride-36 columns
#pragma unroll
        for (int r = 0; r < 2; ++r) {
            int c = t + r * 128;
            const float* row = &snbr[c * 36];
            float sum = 0.f;
#pragma unroll
            for (int q = 0; q < 8; ++q) {
                int qq = (q + rot) & 7;
                float4 v  = *(const float4*)&row[qq * 4];
                float4 wv = *(const float4*)&swgt[qq * 4];
                sum += v.x * wv.x + v.y * wv.y + v.z * wv.z + v.w * wv.w;
            }
            out[((size_t)(b * Hv) + c) * Pv + p] = sum;
        }
    }
}

// ---------------------------------------------------------------------------
extern "C" void kernel_launch(void* const* d_in, const int* in_sizes, int n_in,
                              void* d_out, int out_size)
{
    const float* cur = (const float*)d_in[0];
    const float* nbr = (const float*)d_in[1];
    const float* vld = (const float*)d_in[2];
    const float* edg = (const float*)d_in[3];
    const float* w1  = (const float*)d_in[4];
    const float* b1  = (const float*)d_in[5];
    const float* w2  = (const float*)d_in[6];
    const float* b2  = (const float*)d_in[7];
    float* out = (float*)d_out;

    curterm_kernel<<<128, 256>>>(cur, w1, b1);

    cudaFuncSetAttribute(attn_kernel,
                         cudaFuncAttributeMaxDynamicSharedMemorySize, SMEM_BYTES);
    attn_kernel<<<Bv * Pv, 128, SMEM_BYTES>>>(nbr, vld, edg, w1, w2, b2, out);
}